// round 7
// baseline (speedup 1.0000x reference)
#include <cuda_runtime.h>
#include <cuda_bf16.h>
#include <cstdint>

// RWKV WKV recurrence, single-pass serial-in-T, warp-per-block cp.async ring.
//   a_t = exp(w_t)*a_{t-1} + exp(k_t)
//   b_t = exp(w_t)*b_{t-1} + exp(k_t)*v_t
//   out_t = b_t / a_t
// One 32-thread block per (batch, 32-wide d-group): 512 blocks. Serial walk
// over T=2048 with k/v/w prefetched ~48 steps ahead into a 24KB smem ring.
// R6 change: SPB=16/NB=4 (half the wait/sync events of R5) and fully hoisted
// cp.async address math — with ~1 warp/SMSP, every overhead cycle on the
// demand warp is a DRAM-idle cycle, so minimize per-iteration serial work.
// Minimal traffic: 3 reads + 1 write = 537MB.

#define BATCH 16
#define TLEN  2048
#define DIM   1024
#define GROUP 32
#define SPB   16                       // steps per ring slot
#define NB    4                        // ring depth in slots (48-step lead)
#define NBT   (TLEN / SPB)             // 128 iterations
#define TPT   12                       // cp.async tiles per thread per slot (3*16*8/32)
#define SLOT_BYTES (3 * SPB * GROUP * 4)   // 6144

__device__ __forceinline__ void cp_async16(uint32_t s, const void* g) {
    asm volatile("cp.async.cg.shared.global [%0], [%1], 16;" :: "r"(s), "l"(g));
}

__global__ __launch_bounds__(GROUP, 4)
void wkv_warp_ring_kernel(const float* __restrict__ K,
                          const float* __restrict__ V,
                          const float* __restrict__ W,
                          float* __restrict__ O) {
    // ring[slot][arr][step][d] : slot<4, arr<3, step<16, d<32
    __shared__ float ring[NB * 3 * SPB * GROUP];   // 24 KB

    const int tid = threadIdx.x;
    const int b   = blockIdx.x >> 5;          // batch
    const int g   = blockIdx.x & 31;          // d-group of 32

    const size_t rowBase = (size_t)b * TLEN * DIM + (size_t)g * GROUP;
    const uint32_t sBase = (uint32_t)__cvta_generic_to_shared(ring);

    const float* arrs[3] = { K, V, W };

    // Precompute all per-thread cp.async source pointers / smem offsets once.
    // Tile i = tid + 32*j:  arr = i/128, t = (i%128)/8, col16 = i%8.
    const float* gp[TPT];
    uint32_t     sp[TPT];
#pragma unroll
    for (int j = 0; j < TPT; j++) {
        int i   = tid + GROUP * j;            // 0..383
        int arr = i >> 7;
        int rem = i & 127;
        int t   = rem >> 3;                   // step within slot
        int col = rem & 7;                    // 16B column within 128B row
        gp[j] = arrs[arr] + rowBase + (size_t)t * DIM + (size_t)col * 4;
        sp[j] = sBase + (uint32_t)(((arr * SPB + t) * GROUP + col * 4) * 4);
    }

    // Issue all cp.asyncs for one ring slot: just two added offsets per tile.
    auto issue_batch = [&](int bt) {
        const uint32_t so  = (uint32_t)(bt & (NB - 1)) * SLOT_BYTES;
        const size_t   off = (size_t)bt * (SPB * DIM);
#pragma unroll
        for (int j = 0; j < TPT; j++) cp_async16(sp[j] + so, gp[j] + off);
    };

    // ---- prologue: fill NB-1 ring slots ----
#pragma unroll
    for (int bt = 0; bt < NB - 1; bt++) {
        issue_batch(bt);
        asm volatile("cp.async.commit_group;");
    }

    float a = 0.0f, s = 0.0f;
    float* out = O + rowBase + tid;

    for (int bt = 0; bt < NBT; bt++) {
        // Keep pipeline full; commit every iteration (possibly empty group)
        // so wait_group arithmetic stays uniform through the tail.
        if (bt + NB - 1 < NBT) issue_batch(bt + NB - 1);
        asm volatile("cp.async.commit_group;");
        asm volatile("cp.async.wait_group %0;" :: "n"(NB - 2) : "memory");
        __syncwarp();   // this slot's data visible to all lanes

        const int slot = bt & (NB - 1);
        const float* rk = &ring[((slot * 3 + 0) * SPB) * GROUP + tid];
        const float* rv = &ring[((slot * 3 + 1) * SPB) * GROUP + tid];
        const float* rw = &ring[((slot * 3 + 2) * SPB) * GROUP + tid];

#pragma unroll
        for (int u = 0; u < SPB; u++) {
            float lk = rk[u * GROUP];
            float lv = rv[u * GROUP];
            float lw = rw[u * GROUP];
            float ek = __expf(lk);
            float ew = __expf(lw);
            a = fmaf(ew, a, ek);
            s = fmaf(ew, s, ek * lv);
            __stcs(&out[(size_t)(bt * SPB + u) * DIM], __fdividef(s, a));
        }
        __syncwarp();   // all lanes done reading before slot is overwritten
    }
}

extern "C" void kernel_launch(void* const* d_in, const int* in_sizes, int n_in,
                              void* d_out, int out_size) {
    const float* k = (const float*)d_in[0];
    const float* v = (const float*)d_in[1];
    const float* w = (const float*)d_in[2];
    float* out = (float*)d_out;

    wkv_warp_ring_kernel<<<BATCH * (DIM / GROUP), GROUP>>>(k, v, w, out);
}